// round 14
// baseline (speedup 1.0000x reference)
#include <cuda_runtime.h>
#include <cuda_bf16.h>
#include <math.h>
#include <stdint.h>

// ---------------------------------------------------------------------------
// WideDeep round 14: byte-exact round-8 champion (141.3us) for embed/prep/
// GEMM1/GEMM2. GEMM3 instantiates a templated fused epilogue: instead of
// storing h3, it computes per-row partial dots relu(acc+bias).Wd and
// atomicAdds into g_part (zeroed by embed). Final kernel reduces to sigmoid.
// GEMM1/2 use the <false> instantiation == round-8 SASS.
// ---------------------------------------------------------------------------

#define B_SZ   8192
#define L_TOK  32
#define L_MH   20
#define EMB    64
#define TOK_D  300
#define K1     748
#define K1P    768
#define N1     1024
#define N2     512
#define N3     256

__device__ __align__(16) __nv_bfloat16 g_embB[B_SZ * K1P];
__device__ __align__(16) __nv_bfloat16 g_h1b [B_SZ * N1];
__device__ __align__(16) __nv_bfloat16 g_h2b [B_SZ * N2];
__device__ __align__(16) __nv_bfloat16 g_Wt1 [N1 * K1P];
__device__ __align__(16) __nv_bfloat16 g_Wt2 [N2 * N1];
__device__ __align__(16) __nv_bfloat16 g_Wt3 [N3 * N2];
__device__ float g_wide[B_SZ];
__device__ float g_part[B_SZ];     // fused GEMM3 partial dot accumulator

__device__ __forceinline__ uint32_t smem_u32(const void* p) {
    uint32_t a;
    asm("{ .reg .u64 t; cvta.to.shared.u64 t, %1; cvt.u32.u64 %0, t; }"
        : "=r"(a) : "l"(p));
    return a;
}
__device__ __forceinline__ uint32_t bf2_bits(float x, float y) {
    __nv_bfloat162 v = __floats2bfloat162_rn(x, y);
    return *(uint32_t*)&v;
}

// ---------------------------------------------------------------------------
// Fused kernel 1 (round 8 + g_part zero-init in the wide-tower section):
// blocks [0, 8192) embed; blocks [8192, 9600) weight prep.
// ---------------------------------------------------------------------------
__global__ __launch_bounds__(256) void embed_prep_kernel(
    const int* __restrict__ tok, const int* __restrict__ m1,
    const int* __restrict__ m2,  const int* __restrict__ m3,
    const int* __restrict__ o1,  const int* __restrict__ o2,
    const int* __restrict__ o3,  const int* __restrict__ o4,
    const float* __restrict__ we,
    const float* __restrict__ em1, const float* __restrict__ em2,
    const float* __restrict__ em3,
    const float* __restrict__ eo1, const float* __restrict__ eo2,
    const float* __restrict__ eo3, const float* __restrict__ eo4,
    const float* __restrict__ wm1, const float* __restrict__ wm2,
    const float* __restrict__ wm3,
    const float* __restrict__ wo1, const float* __restrict__ wo2,
    const float* __restrict__ wo3, const float* __restrict__ wo4,
    const float* __restrict__ W1, const float* __restrict__ W2,
    const float* __restrict__ W3)
{
    const int tid = threadIdx.x;

    if (blockIdx.x >= B_SZ) {
        __shared__ float tile[32][33];
        const int bid = blockIdx.x - B_SZ;

        const float* W; __nv_bfloat16* Wt; int K, N, Kpad, t;
        if (bid < 768)       { W = W1; Wt = g_Wt1; K = K1; N = N1; Kpad = K1P; t = bid; }
        else if (bid < 1280) { W = W2; Wt = g_Wt2; K = N1; N = N2; Kpad = N1;  t = bid - 768; }
        else                 { W = W3; Wt = g_Wt3; K = N2; N = N3; Kpad = N2;  t = bid - 1280; }

        const int ktiles = Kpad >> 5;
        const int tk = t % ktiles, tn = t / ktiles;
        const int tx = tid & 31, ty = tid >> 5;

        #pragma unroll
        for (int i = 0; i < 4; i++) {
            const int k = tk * 32 + ty + i * 8;
            tile[tx][ty + i * 8] = (k < K) ? W[(size_t)k * N + tn * 32 + tx] : 0.f;
        }
        __syncthreads();

        const int p = tid & 15;
        #pragma unroll
        for (int h = 0; h < 2; h++) {
            const int n = (tid >> 4) + 16 * h;
            const uint32_t v = bf2_bits(tile[n][2 * p], tile[n][2 * p + 1]);
            *(uint32_t*)(Wt + (size_t)(tn * 32 + n) * Kpad + tk * 32 + p * 2) = v;
        }
        return;
    }

    const int b = blockIdx.x;

    __shared__ int s_tok[L_TOK];
    __shared__ int s_m1[L_MH], s_m2[L_MH], s_m3[L_MH];
    __shared__ int s_oh[4];
    __shared__ float4 s_part[2][75];

    if (tid < 32)       s_tok[tid]      = tok[b * L_TOK + tid];
    else if (tid < 52)  s_m1[tid - 32]  = m1[b * L_MH + tid - 32];
    else if (tid < 72)  s_m2[tid - 52]  = m2[b * L_MH + tid - 52];
    else if (tid < 92)  s_m3[tid - 72]  = m3[b * L_MH + tid - 72];
    else if (tid == 92) s_oh[0] = o1[b];
    else if (tid == 93) s_oh[1] = o2[b];
    else if (tid == 94) s_oh[2] = o3[b];
    else if (tid == 95) s_oh[3] = o4[b];
    __syncthreads();

    __nv_bfloat16* eb = g_embB + (size_t)b * K1P;

    float4 acc = make_float4(0.f, 0.f, 0.f, 0.f);
    if (tid < 225) {
        const int c = tid % 75, g = tid / 75;
        const int j0 = g * 11, j1 = (g < 2) ? j0 + 11 : 32;
        for (int j = j0; j < j1; j++) {
            const float4 v = *(const float4*)(we + (size_t)s_tok[j] * TOK_D + c * 4);
            acc.x += v.x; acc.y += v.y; acc.z += v.z; acc.w += v.w;
        }
        if (g > 0) s_part[g - 1][c] = acc;
    }

    if (tid >= 228 && tid < 233)
        ((uint2*)(eb + K1))[tid - 228] = make_uint2(0u, 0u);

    __syncthreads();

    if (tid < 75) {
        float4 t = acc;
        const float4 p0 = s_part[0][tid], p1 = s_part[1][tid];
        t.x = (t.x + p0.x + p1.x) * (1.0f / 32.0f);
        t.y = (t.y + p0.y + p1.y) * (1.0f / 32.0f);
        t.z = (t.z + p0.z + p1.z) * (1.0f / 32.0f);
        t.w = (t.w + p0.w + p1.w) * (1.0f / 32.0f);
        ((uint2*)eb)[tid] = make_uint2(bf2_bits(t.x, t.y), bf2_bits(t.z, t.w));
    } else if (tid >= 80 && tid < 128) {
        const int f = (tid - 80) >> 4, c = (tid - 80) & 15;
        const float* tab = (f == 0) ? em1 : (f == 1) ? em2 : em3;
        const int* sidx = (f == 0) ? s_m1 : (f == 1) ? s_m2 : s_m3;
        float4 s = make_float4(0.f, 0.f, 0.f, 0.f);
        #pragma unroll
        for (int j = 0; j < L_MH; j++) {
            const float4 v = *(const float4*)(tab + (size_t)sidx[j] * EMB + c * 4);
            s.x += v.x; s.y += v.y; s.z += v.z; s.w += v.w;
        }
        __nv_bfloat16* dst = eb + 300 + f * 64 + c * 4;
        *(uint2*)dst = make_uint2(bf2_bits(s.x * 0.05f, s.y * 0.05f),
                                  bf2_bits(s.z * 0.05f, s.w * 0.05f));
    } else if (tid >= 128 && tid < 192) {
        const int f = (tid - 128) >> 4, c = (tid - 128) & 15;
        const float* tab = (f == 0) ? eo1 : (f == 1) ? eo2 : (f == 2) ? eo3 : eo4;
        const float4 v = *(const float4*)(tab + (size_t)s_oh[f] * EMB + c * 4);
        __nv_bfloat16* dst = eb + 492 + f * 64 + c * 4;
        *(uint2*)dst = make_uint2(bf2_bits(v.x, v.y), bf2_bits(v.z, v.w));
    } else if (tid >= 192 && tid < 224) {
        const int lane = tid - 192;
        if (lane == 1) g_part[b] = 0.f;          // zero fused-GEMM3 accumulator
        float s = 0.f;
        if (lane < L_MH)
            s = wm1[s_m1[lane]] + wm2[s_m2[lane]] + wm3[s_m3[lane]];
        #pragma unroll
        for (int o = 16; o; o >>= 1) s += __shfl_xor_sync(0xFFFFFFFFu, s, o);
        if (lane == 0) {
            s += wo1[s_oh[0]] + wo2[s_oh[1]] + wo3[s_oh[2]] + wo4[s_oh[3]];
            g_wide[b] = s;
        }
    }
}

// ---------------------------------------------------------------------------
// Tensor-core GEMM (round-8 mainloop, untouched):
// FUSE_FINAL=false: C = relu(A@Bt^T + bias) -> bf16           (GEMM1, GEMM2)
// FUSE_FINAL=true : g_part[row] += relu(acc+bias).Wd[cols]    (GEMM3)
// 128x128x64 CTA tile, 256 thr, mma m16n8k16, 3-stage cp.async (96 KB),
// ldmatrix.x4, 8-chunk XOR swizzle.
// ---------------------------------------------------------------------------
__device__ __forceinline__ void mma16816(float c[4], const uint32_t a[4],
                                         const uint32_t b[2])
{
    asm volatile(
        "mma.sync.aligned.m16n8k16.row.col.f32.bf16.bf16.f32 "
        "{%0,%1,%2,%3}, {%4,%5,%6,%7}, {%8,%9}, {%0,%1,%2,%3};"
        : "+f"(c[0]), "+f"(c[1]), "+f"(c[2]), "+f"(c[3])
        : "r"(a[0]), "r"(a[1]), "r"(a[2]), "r"(a[3]), "r"(b[0]), "r"(b[1]));
}

#define STAGE_BYTES 32768           // A 16K + B 16K (128 rows x 128 B each)

template <bool FUSE_FINAL>
__global__ __launch_bounds__(256, 2) void gemm_tc_kernel(
    const __nv_bfloat16* __restrict__ A, const __nv_bfloat16* __restrict__ Bt,
    const float* __restrict__ bias, const float* __restrict__ Wd,
    __nv_bfloat16* __restrict__ C, int Nout, int K)
{
    extern __shared__ __align__(1024) char sm[];   // 3 * STAGE_BYTES

    const int tid  = threadIdx.x;
    const int lane = tid & 31, warp = tid >> 5;
    const int wm   = warp & 1;
    const int wn   = warp >> 1;
    const int gid  = lane >> 2;
    const int tig  = lane & 3;
    const int bm   = blockIdx.y * 128, bn = blockIdx.x * 128;

    int offS[4], gA[4], gB[4];
    #pragma unroll
    for (int j = 0; j < 4; j++) {
        const int c = tid + j * 256;
        const int r = c >> 3, ch = c & 7;
        offS[j] = r * 128 + ((ch ^ (r & 7)) << 4);
        gA[j]   = (bm + r) * K + ch * 8;
        gB[j]   = (bn + r) * K + ch * 8;
    }

    const int NIT = K >> 6;   // K / 64

    const int q = lane >> 3, r8 = lane & 7;
    const int qa = q >> 1, qb = q & 1;
    uint32_t arow128[4]; int akey[4];
    #pragma unroll
    for (int mf = 0; mf < 4; mf++) {
        const int row = wm * 64 + mf * 16 + (q & 1) * 8 + r8;
        arow128[mf] = row * 128;
        akey[mf]    = row & 7;
    }
    uint32_t brow128[2]; int bkey[2];
    #pragma unroll
    for (int g = 0; g < 2; g++) {
        const int row = wn * 32 + g * 16 + (q >> 1) * 8 + r8;
        brow128[g] = row * 128;
        bkey[g]    = row & 7;
    }

    float acc[4][4][4];
    #pragma unroll
    for (int mf = 0; mf < 4; mf++)
        #pragma unroll
        for (int nf = 0; nf < 4; nf++)
            #pragma unroll
            for (int i = 0; i < 4; i++) acc[mf][nf][i] = 0.f;

    #define PREFETCH(stage, kofs)                                              \
        do {                                                                   \
            char* _s = sm + (stage) * STAGE_BYTES;                             \
            _Pragma("unroll")                                                  \
            for (int _j = 0; _j < 4; _j++) {                                   \
                uint32_t _da = smem_u32(_s + offS[_j]);                        \
                uint32_t _db = _da + 16384;                                    \
                asm volatile("cp.async.cg.shared.global [%0], [%1], 16;"       \
                             :: "r"(_da), "l"(A + gA[_j] + (kofs)) : "memory");\
                asm volatile("cp.async.cg.shared.global [%0], [%1], 16;"       \
                             :: "r"(_db), "l"(Bt + gB[_j] + (kofs)) : "memory");\
            }                                                                  \
        } while (0)

    PREFETCH(0, 0);
    asm volatile("cp.async.commit_group;" ::: "memory");
    PREFETCH(1, 64);
    asm volatile("cp.async.commit_group;" ::: "memory");

    for (int it = 0; it < NIT; it++) {
        asm volatile("cp.async.wait_group 1;" ::: "memory");
        __syncthreads();

        if (it + 2 < NIT) {
            const int st = it + 2;
            PREFETCH(st % 3, st * 64);
        }
        asm volatile("cp.async.commit_group;" ::: "memory");

        const uint32_t AsU = smem_u32(sm + (it % 3) * STAGE_BYTES);
        const uint32_t BsU = AsU + 16384;

        #pragma unroll
        for (int s = 0; s < 4; s++) {
            uint32_t af[4][4], bf[4][2];
            #pragma unroll
            for (int mf = 0; mf < 4; mf++) {
                const uint32_t addr =
                    AsU + arow128[mf] + ((((s << 1) + qa) ^ akey[mf]) << 4);
                asm volatile(
                    "ldmatrix.sync.aligned.m8n8.x4.shared.b16 {%0,%1,%2,%3}, [%4];"
                    : "=r"(af[mf][0]), "=r"(af[mf][1]),
                      "=r"(af[mf][2]), "=r"(af[mf][3])
                    : "r"(addr));
            }
            #pragma unroll
            for (int g = 0; g < 2; g++) {
                const uint32_t addr =
                    BsU + brow128[g] + ((((s << 1) + qb) ^ bkey[g]) << 4);
                asm volatile(
                    "ldmatrix.sync.aligned.m8n8.x4.shared.b16 {%0,%1,%2,%3}, [%4];"
                    : "=r"(bf[2 * g][0]), "=r"(bf[2 * g][1]),
                      "=r"(bf[2 * g + 1][0]), "=r"(bf[2 * g + 1][1])
                    : "r"(addr));
            }
            #pragma unroll
            for (int mf = 0; mf < 4; mf++)
                #pragma unroll
                for (int nf = 0; nf < 4; nf++)
                    mma16816(acc[mf][nf], af[mf], bf[nf]);
        }
    }
    #undef PREFETCH

    if (FUSE_FINAL) {
        // per-row partial dot with Wd: quad shfl-reduce, atomicAdd to g_part
        float rs0[4] = {0.f, 0.f, 0.f, 0.f};
        float rs1[4] = {0.f, 0.f, 0.f, 0.f};
        #pragma unroll
        for (int nf = 0; nf < 4; nf++) {
            const int col = bn + wn * 32 + nf * 8 + tig * 2;
            const float bv0 = bias[col], bv1 = bias[col + 1];
            const float wd0 = Wd[col],  wd1 = Wd[col + 1];
            #pragma unroll
            for (int mf = 0; mf < 4; mf++) {
                rs0[mf] += fmaxf(acc[mf][nf][0] + bv0, 0.f) * wd0
                         + fmaxf(acc[mf][nf][1] + bv1, 0.f) * wd1;
                rs1[mf] += fmaxf(acc[mf][nf][2] + bv0, 0.f) * wd0
                         + fmaxf(acc[mf][nf][3] + bv1, 0.f) * wd1;
            }
        }
        #pragma unroll
        for (int mf = 0; mf < 4; mf++) {
            rs0[mf] += __shfl_xor_sync(0xFFFFFFFFu, rs0[mf], 1);
            rs0[mf] += __shfl_xor_sync(0xFFFFFFFFu, rs0[mf], 2);
            rs1[mf] += __shfl_xor_sync(0xFFFFFFFFu, rs1[mf], 1);
            rs1[mf] += __shfl_xor_sync(0xFFFFFFFFu, rs1[mf], 2);
            if (tig == 0) {
                const int row0 = bm + wm * 64 + mf * 16 + gid;
                atomicAdd(&g_part[row0],     rs0[mf]);
                atomicAdd(&g_part[row0 + 8], rs1[mf]);
            }
        }
    } else {
        #pragma unroll
        for (int nf = 0; nf < 4; nf++) {
            const int col = bn + wn * 32 + nf * 8 + tig * 2;
            const float bv0 = bias[col], bv1 = bias[col + 1];
            #pragma unroll
            for (int mf = 0; mf < 4; mf++) {
                const int row0 = bm + wm * 64 + mf * 16 + gid;
                const float v00 = fmaxf(acc[mf][nf][0] + bv0, 0.f);
                const float v01 = fmaxf(acc[mf][nf][1] + bv1, 0.f);
                const float v10 = fmaxf(acc[mf][nf][2] + bv0, 0.f);
                const float v11 = fmaxf(acc[mf][nf][3] + bv1, 0.f);
                *(__nv_bfloat162*)(C + (size_t)row0 * Nout + col) =
                    __floats2bfloat162_rn(v00, v01);
                *(__nv_bfloat162*)(C + (size_t)(row0 + 8) * Nout + col) =
                    __floats2bfloat162_rn(v10, v11);
            }
        }
    }
}

// ---------------------------------------------------------------------------
// Final: out = sigmoid(g_part + bd + wide). One thread per row.
// ---------------------------------------------------------------------------
__global__ __launch_bounds__(256) void final_kernel(
    const float* __restrict__ bd, float* __restrict__ out)
{
    const int b = blockIdx.x * 256 + threadIdx.x;
    const float logit = g_part[b] + bd[0] + g_wide[b];
    out[b] = 1.0f / (1.0f + expf(-logit));
}

// ---------------------------------------------------------------------------
extern "C" void kernel_launch(void* const* d_in, const int* in_sizes, int n_in,
                              void* d_out, int out_size)
{
    (void)in_sizes; (void)n_in; (void)out_size;

    const int*   tok = (const int*)d_in[0];
    const int*   m1  = (const int*)d_in[1];
    const int*   m2  = (const int*)d_in[2];
    const int*   m3  = (const int*)d_in[3];
    const int*   o1  = (const int*)d_in[4];
    const int*   o2  = (const int*)d_in[5];
    const int*   o3  = (const int*)d_in[6];
    const int*   o4  = (const int*)d_in[7];
    const float* we  = (const float*)d_in[8];
    const float* em1 = (const float*)d_in[9];
    const float* em2 = (const float*)d_in[10];
    const float* em3 = (const float*)d_in[11];
    const float* eo1 = (const float*)d_in[12];
    const float* eo2 = (const float*)d_in[13];
    const float* eo3 = (const float*)d_in[14];
    const float* eo4 = (const float*)d_in[15];
    const float* wm1 = (const float*)d_in[16];
    const float* wm2 = (const float*)d_in[17];
    const float* wm3 = (const float*)d_in[18];
    const float* wo1 = (const float*)d_in[19];
    const float* wo2 = (const float*)d_in[20];
    const float* wo3 = (const float*)d_in[21];
    const float* wo4 = (const float*)d_in[22];
    const float* W1  = (const float*)d_in[23];
    const float* b1  = (const float*)d_in[24];
    const float* W2  = (const float*)d_in[25];
    const float* b2  = (const float*)d_in[26];
    const float* W3  = (const float*)d_in[27];
    const float* b3  = (const float*)d_in[28];
    const float* Wd  = (const float*)d_in[29];
    const float* bd  = (const float*)d_in[30];
    float* out = (float*)d_out;

    void *p_embB, *p_h1, *p_h2, *p_wt1, *p_wt2, *p_wt3;
    cudaGetSymbolAddress(&p_embB, g_embB);
    cudaGetSymbolAddress(&p_h1,   g_h1b);
    cudaGetSymbolAddress(&p_h2,   g_h2b);
    cudaGetSymbolAddress(&p_wt1,  g_Wt1);
    cudaGetSymbolAddress(&p_wt2,  g_Wt2);
    cudaGetSymbolAddress(&p_wt3,  g_Wt3);

    const int SMEM_DYN = 3 * STAGE_BYTES;   // 96 KB
    static int smem_set = 0;
    if (!smem_set) {
        cudaFuncSetAttribute(gemm_tc_kernel<false>,
                             cudaFuncAttributeMaxDynamicSharedMemorySize, SMEM_DYN);
        cudaFuncSetAttribute(gemm_tc_kernel<true>,
                             cudaFuncAttributeMaxDynamicSharedMemorySize, SMEM_DYN);
        smem_set = 1;
    }

    embed_prep_kernel<<<B_SZ + 768 + 512 + 128, 256>>>(
        tok, m1, m2, m3, o1, o2, o3, o4,
        we, em1, em2, em3, eo1, eo2, eo3, eo4,
        wm1, wm2, wm3, wo1, wo2, wo3, wo4,
        W1, W2, W3);

    gemm_tc_kernel<false><<<dim3(N1 / 128, B_SZ / 128), 256, SMEM_DYN>>>(
        (const __nv_bfloat16*)p_embB, (const __nv_bfloat16*)p_wt1, b1, nullptr,
        (__nv_bfloat16*)p_h1, N1, K1P);
    gemm_tc_kernel<false><<<dim3(N2 / 128, B_SZ / 128), 256, SMEM_DYN>>>(
        (const __nv_bfloat16*)p_h1, (const __nv_bfloat16*)p_wt2, b2, nullptr,
        (__nv_bfloat16*)p_h2, N2, N1);
    gemm_tc_kernel<true><<<dim3(N3 / 128, B_SZ / 128), 256, SMEM_DYN>>>(
        (const __nv_bfloat16*)p_h2, (const __nv_bfloat16*)p_wt3, b3, Wd,
        nullptr, N3, N2);

    final_kernel<<<B_SZ / 256, 256>>>(bd, out);
}

// round 15
// speedup vs baseline: 1.0959x; 1.0959x over previous
#include <cuda_runtime.h>
#include <cuda_bf16.h>
#include <math.h>
#include <stdint.h>

// ---------------------------------------------------------------------------
// WideDeep round 15: round-8 champion everywhere, plus ONE structural change:
// embedding tables (word_emb, em1/2/3) are converted to bf16 by a small
// convert kernel each invocation, halving the embed kernel's L2 gather
// traffic (~440MB -> ~220MB). Token-loop structure preserved verbatim.
// ---------------------------------------------------------------------------

#define B_SZ   8192
#define L_TOK  32
#define L_MH   20
#define EMB    64
#define TOK_D  300
#define K1     748
#define K1P    768
#define N1     1024
#define N2     512
#define N3     256

__device__ __align__(16) __nv_bfloat16 g_embB[B_SZ * K1P];
__device__ __align__(16) __nv_bfloat16 g_h1b [B_SZ * N1];
__device__ __align__(16) __nv_bfloat16 g_h2b [B_SZ * N2];
__device__ __align__(16) __nv_bfloat16 g_h3b [B_SZ * N3];
__device__ __align__(16) __nv_bfloat16 g_Wt1 [N1 * K1P];
__device__ __align__(16) __nv_bfloat16 g_Wt2 [N2 * N1];
__device__ __align__(16) __nv_bfloat16 g_Wt3 [N3 * N2];
__device__ float g_wide[B_SZ];

// bf16 copies of the gathered tables
__device__ __align__(16) __nv_bfloat16 g_weB [50000 * TOK_D];   // 30 MB
__device__ __align__(16) __nv_bfloat16 g_em1B[1000  * EMB];
__device__ __align__(16) __nv_bfloat16 g_em2B[5000  * EMB];
__device__ __align__(16) __nv_bfloat16 g_em3B[10000 * EMB];

__device__ __forceinline__ uint32_t smem_u32(const void* p) {
    uint32_t a;
    asm("{ .reg .u64 t; cvta.to.shared.u64 t, %1; cvt.u32.u64 %0, t; }"
        : "=r"(a) : "l"(p));
    return a;
}
__device__ __forceinline__ uint32_t bf2_bits(float x, float y) {
    __nv_bfloat162 v = __floats2bfloat162_rn(x, y);
    return *(uint32_t*)&v;
}

// ---------------------------------------------------------------------------
// Kernel 0: fp32 -> bf16 table conversion (one float4 -> uint2 per thread).
//   word_emb: 3,750,000 float4;  em1: 16,000;  em2: 80,000;  em3: 160,000
// ---------------------------------------------------------------------------
#define CV_WE  3750000
#define CV_M1  (CV_WE + 16000)
#define CV_M2  (CV_M1 + 80000)
#define CV_TOT (CV_M2 + 160000)

__global__ __launch_bounds__(256) void convert_kernel(
    const float* __restrict__ we,  const float* __restrict__ em1,
    const float* __restrict__ em2, const float* __restrict__ em3)
{
    size_t i = (size_t)blockIdx.x * 256 + threadIdx.x;
    if (i >= CV_TOT) return;

    const float* src; __nv_bfloat16* dst; size_t off;
    if (i < CV_WE)      { src = we;  dst = g_weB;  off = i; }
    else if (i < CV_M1) { src = em1; dst = g_em1B; off = i - CV_WE; }
    else if (i < CV_M2) { src = em2; dst = g_em2B; off = i - CV_M1; }
    else                { src = em3; dst = g_em3B; off = i - CV_M2; }

    const float4 v = ((const float4*)src)[off];
    ((uint2*)dst)[off] = make_uint2(bf2_bits(v.x, v.y), bf2_bits(v.z, v.w));
}

// ---------------------------------------------------------------------------
// Fused kernel 1 (round-8 structure; token/mh gathers now read bf16 tables):
// blocks [0, 8192) embed; blocks [8192, 9600) weight prep.
// ---------------------------------------------------------------------------
__global__ __launch_bounds__(256) void embed_prep_kernel(
    const int* __restrict__ tok, const int* __restrict__ m1,
    const int* __restrict__ m2,  const int* __restrict__ m3,
    const int* __restrict__ o1,  const int* __restrict__ o2,
    const int* __restrict__ o3,  const int* __restrict__ o4,
    const float* __restrict__ eo1, const float* __restrict__ eo2,
    const float* __restrict__ eo3, const float* __restrict__ eo4,
    const float* __restrict__ wm1, const float* __restrict__ wm2,
    const float* __restrict__ wm3,
    const float* __restrict__ wo1, const float* __restrict__ wo2,
    const float* __restrict__ wo3, const float* __restrict__ wo4,
    const float* __restrict__ W1, const float* __restrict__ W2,
    const float* __restrict__ W3)
{
    const int tid = threadIdx.x;

    if (blockIdx.x >= B_SZ) {
        __shared__ float tile[32][33];
        const int bid = blockIdx.x - B_SZ;

        const float* W; __nv_bfloat16* Wt; int K, N, Kpad, t;
        if (bid < 768)       { W = W1; Wt = g_Wt1; K = K1; N = N1; Kpad = K1P; t = bid; }
        else if (bid < 1280) { W = W2; Wt = g_Wt2; K = N1; N = N2; Kpad = N1;  t = bid - 768; }
        else                 { W = W3; Wt = g_Wt3; K = N2; N = N3; Kpad = N2;  t = bid - 1280; }

        const int ktiles = Kpad >> 5;
        const int tk = t % ktiles, tn = t / ktiles;
        const int tx = tid & 31, ty = tid >> 5;

        #pragma unroll
        for (int i = 0; i < 4; i++) {
            const int k = tk * 32 + ty + i * 8;
            tile[tx][ty + i * 8] = (k < K) ? W[(size_t)k * N + tn * 32 + tx] : 0.f;
        }
        __syncthreads();

        const int p = tid & 15;
        #pragma unroll
        for (int h = 0; h < 2; h++) {
            const int n = (tid >> 4) + 16 * h;
            const uint32_t v = bf2_bits(tile[n][2 * p], tile[n][2 * p + 1]);
            *(uint32_t*)(Wt + (size_t)(tn * 32 + n) * Kpad + tk * 32 + p * 2) = v;
        }
        return;
    }

    const int b = blockIdx.x;

    __shared__ int s_tok[L_TOK];
    __shared__ int s_m1[L_MH], s_m2[L_MH], s_m3[L_MH];
    __shared__ int s_oh[4];
    __shared__ float4 s_part[2][75];

    if (tid < 32)       s_tok[tid]      = tok[b * L_TOK + tid];
    else if (tid < 52)  s_m1[tid - 32]  = m1[b * L_MH + tid - 32];
    else if (tid < 72)  s_m2[tid - 52]  = m2[b * L_MH + tid - 52];
    else if (tid < 92)  s_m3[tid - 72]  = m3[b * L_MH + tid - 72];
    else if (tid == 92) s_oh[0] = o1[b];
    else if (tid == 93) s_oh[1] = o2[b];
    else if (tid == 94) s_oh[2] = o3[b];
    else if (tid == 95) s_oh[3] = o4[b];
    __syncthreads();

    __nv_bfloat16* eb = g_embB + (size_t)b * K1P;

    // token bag mean: same structure as round 8, bf16 uint2 loads (8 B)
    float4 acc = make_float4(0.f, 0.f, 0.f, 0.f);
    if (tid < 225) {
        const int c = tid % 75, g = tid / 75;
        const int j0 = g * 11, j1 = (g < 2) ? j0 + 11 : 32;
        for (int j = j0; j < j1; j++) {
            const uint2 u = *(const uint2*)(g_weB + (size_t)s_tok[j] * TOK_D + c * 4);
            const float2 f0 = __bfloat1622float2(*(const __nv_bfloat162*)&u.x);
            const float2 f1 = __bfloat1622float2(*(const __nv_bfloat162*)&u.y);
            acc.x += f0.x; acc.y += f0.y; acc.z += f1.x; acc.w += f1.y;
        }
        if (g > 0) s_part[g - 1][c] = acc;
    }

    if (tid >= 228 && tid < 233)
        ((uint2*)(eb + K1))[tid - 228] = make_uint2(0u, 0u);

    __syncthreads();

    if (tid < 75) {
        float4 t = acc;
        const float4 p0 = s_part[0][tid], p1 = s_part[1][tid];
        t.x = (t.x + p0.x + p1.x) * (1.0f / 32.0f);
        t.y = (t.y + p0.y + p1.y) * (1.0f / 32.0f);
        t.z = (t.z + p0.z + p1.z) * (1.0f / 32.0f);
        t.w = (t.w + p0.w + p1.w) * (1.0f / 32.0f);
        ((uint2*)eb)[tid] = make_uint2(bf2_bits(t.x, t.y), bf2_bits(t.z, t.w));
    } else if (tid >= 80 && tid < 128) {
        const int f = (tid - 80) >> 4, c = (tid - 80) & 15;
        const __nv_bfloat16* tab = (f == 0) ? g_em1B : (f == 1) ? g_em2B : g_em3B;
        const int* sidx = (f == 0) ? s_m1 : (f == 1) ? s_m2 : s_m3;
        float4 s = make_float4(0.f, 0.f, 0.f, 0.f);
        #pragma unroll
        for (int j = 0; j < L_MH; j++) {
            const uint2 u = *(const uint2*)(tab + (size_t)sidx[j] * EMB + c * 4);
            const float2 f0 = __bfloat1622float2(*(const __nv_bfloat162*)&u.x);
            const float2 f1 = __bfloat1622float2(*(const __nv_bfloat162*)&u.y);
            s.x += f0.x; s.y += f0.y; s.z += f1.x; s.w += f1.y;
        }
        __nv_bfloat16* dst = eb + 300 + f * 64 + c * 4;
        *(uint2*)dst = make_uint2(bf2_bits(s.x * 0.05f, s.y * 0.05f),
                                  bf2_bits(s.z * 0.05f, s.w * 0.05f));
    } else if (tid >= 128 && tid < 192) {
        const int f = (tid - 128) >> 4, c = (tid - 128) & 15;
        const float* tab = (f == 0) ? eo1 : (f == 1) ? eo2 : (f == 2) ? eo3 : eo4;
        const float4 v = *(const float4*)(tab + (size_t)s_oh[f] * EMB + c * 4);
        __nv_bfloat16* dst = eb + 492 + f * 64 + c * 4;
        *(uint2*)dst = make_uint2(bf2_bits(v.x, v.y), bf2_bits(v.z, v.w));
    } else if (tid >= 192 && tid < 224) {
        const int lane = tid - 192;
        float s = 0.f;
        if (lane < L_MH)
            s = wm1[s_m1[lane]] + wm2[s_m2[lane]] + wm3[s_m3[lane]];
        #pragma unroll
        for (int o = 16; o; o >>= 1) s += __shfl_xor_sync(0xFFFFFFFFu, s, o);
        if (lane == 0) {
            s += wo1[s_oh[0]] + wo2[s_oh[1]] + wo3[s_oh[2]] + wo4[s_oh[3]];
            g_wide[b] = s;
        }
    }
}

// ---------------------------------------------------------------------------
// Tensor-core GEMM (byte-exact round-8 champion):
// C = relu(A[M,K] @ Bt[N,K]^T + bias) -> bf16
// 128x128x64 CTA tile, 256 thr, mma m16n8k16, 3-stage cp.async (96 KB),
// ldmatrix.x4, 8-chunk XOR swizzle.
// ---------------------------------------------------------------------------
__device__ __forceinline__ void mma16816(float c[4], const uint32_t a[4],
                                         const uint32_t b[2])
{
    asm volatile(
        "mma.sync.aligned.m16n8k16.row.col.f32.bf16.bf16.f32 "
        "{%0,%1,%2,%3}, {%4,%5,%6,%7}, {%8,%9}, {%0,%1,%2,%3};"
        : "+f"(c[0]), "+f"(c[1]), "+f"(c[2]), "+f"(c[3])
        : "r"(a[0]), "r"(a[1]), "r"(a[2]), "r"(a[3]), "r"(b[0]), "r"(b[1]));
}

#define STAGE_BYTES 32768           // A 16K + B 16K (128 rows x 128 B each)

__global__ __launch_bounds__(256, 2) void gemm_tc_kernel(
    const __nv_bfloat16* __restrict__ A, const __nv_bfloat16* __restrict__ Bt,
    const float* __restrict__ bias, __nv_bfloat16* __restrict__ C,
    int Nout, int K)
{
    extern __shared__ __align__(1024) char sm[];   // 3 * STAGE_BYTES

    const int tid  = threadIdx.x;
    const int lane = tid & 31, warp = tid >> 5;
    const int wm   = warp & 1;
    const int wn   = warp >> 1;
    const int gid  = lane >> 2;
    const int tig  = lane & 3;
    const int bm   = blockIdx.y * 128, bn = blockIdx.x * 128;

    int offS[4], gA[4], gB[4];
    #pragma unroll
    for (int j = 0; j < 4; j++) {
        const int c = tid + j * 256;
        const int r = c >> 3, ch = c & 7;
        offS[j] = r * 128 + ((ch ^ (r & 7)) << 4);
        gA[j]   = (bm + r) * K + ch * 8;
        gB[j]   = (bn + r) * K + ch * 8;
    }

    const int NIT = K >> 6;   // K / 64

    const int q = lane >> 3, r8 = lane & 7;
    const int qa = q >> 1, qb = q & 1;
    uint32_t arow128[4]; int akey[4];
    #pragma unroll
    for (int mf = 0; mf < 4; mf++) {
        const int row = wm * 64 + mf * 16 + (q & 1) * 8 + r8;
        arow128[mf] = row * 128;
        akey[mf]    = row & 7;
    }
    uint32_t brow128[2]; int bkey[2];
    #pragma unroll
    for (int g = 0; g < 2; g++) {
        const int row = wn * 32 + g * 16 + (q >> 1) * 8 + r8;
        brow128[g] = row * 128;
        bkey[g]    = row & 7;
    }

    float acc[4][4][4];
    #pragma unroll
    for (int mf = 0; mf < 4; mf++)
        #pragma unroll
        for (int nf = 0; nf < 4; nf++)
            #pragma unroll
            for (int i = 0; i < 4; i++) acc[mf][nf][i] = 0.f;

    #define PREFETCH(stage, kofs)                                              \
        do {                                                                   \
            char* _s = sm + (stage) * STAGE_BYTES;                             \
            _Pragma("unroll")                                                  \
            for (int _j = 0; _j < 4; _j++) {                                   \
                uint32_t _da = smem_u32(_s + offS[_j]);                        \
                uint32_t _db = _da + 16384;                                    \
                asm volatile("cp.async.cg.shared.global [%0], [%1], 16;"       \
                             :: "r"(_da), "l"(A + gA[_j] + (kofs)) : "memory");\
                asm volatile("cp.async.cg.shared.global [%0], [%1], 16;"       \
                             :: "r"(_db), "l"(Bt + gB[_j] + (kofs)) : "memory");\
            }                                                                  \
        } while (0)

    PREFETCH(0, 0);
    asm volatile("cp.async.commit_group;" ::: "memory");
    PREFETCH(1, 64);
    asm volatile("cp.async.commit_group;" ::: "memory");

    for (int it = 0; it < NIT; it++) {
        asm volatile("cp.async.wait_group 1;" ::: "memory");
        __syncthreads();

        if (it + 2 < NIT) {
            const int st = it + 2;
            PREFETCH(st % 3, st * 64);
        }
        asm volatile("cp.async.commit_group;" ::: "memory");

        const uint32_t AsU = smem_u32(sm + (it % 3) * STAGE_BYTES);
        const uint32_t BsU = AsU + 16384;

        #pragma unroll
        for (int s = 0; s < 4; s++) {
            uint32_t af[4][4], bf[4][2];
            #pragma unroll
            for (int mf = 0; mf < 4; mf++) {
                const uint32_t addr =
                    AsU + arow128[mf] + ((((s << 1) + qa) ^ akey[mf]) << 4);
                asm volatile(
                    "ldmatrix.sync.aligned.m8n8.x4.shared.b16 {%0,%1,%2,%3}, [%4];"
                    : "=r"(af[mf][0]), "=r"(af[mf][1]),
                      "=r"(af[mf][2]), "=r"(af[mf][3])
                    : "r"(addr));
            }
            #pragma unroll
            for (int g = 0; g < 2; g++) {
                const uint32_t addr =
                    BsU + brow128[g] + ((((s << 1) + qb) ^ bkey[g]) << 4);
                asm volatile(
                    "ldmatrix.sync.aligned.m8n8.x4.shared.b16 {%0,%1,%2,%3}, [%4];"
                    : "=r"(bf[2 * g][0]), "=r"(bf[2 * g][1]),
                      "=r"(bf[2 * g + 1][0]), "=r"(bf[2 * g + 1][1])
                    : "r"(addr));
            }
            #pragma unroll
            for (int mf = 0; mf < 4; mf++)
                #pragma unroll
                for (int nf = 0; nf < 4; nf++)
                    mma16816(acc[mf][nf], af[mf], bf[nf]);
        }
    }
    #undef PREFETCH

    // epilogue: bias + ReLU -> bf16
    #pragma unroll
    for (int nf = 0; nf < 4; nf++) {
        const int col = bn + wn * 32 + nf * 8 + tig * 2;
        const float bv0 = bias[col], bv1 = bias[col + 1];
        #pragma unroll
        for (int mf = 0; mf < 4; mf++) {
            const int row0 = bm + wm * 64 + mf * 16 + gid;
            const float v00 = fmaxf(acc[mf][nf][0] + bv0, 0.f);
            const float v01 = fmaxf(acc[mf][nf][1] + bv1, 0.f);
            const float v10 = fmaxf(acc[mf][nf][2] + bv0, 0.f);
            const float v11 = fmaxf(acc[mf][nf][3] + bv1, 0.f);
            *(__nv_bfloat162*)(C + (size_t)row0 * Nout + col) =
                __floats2bfloat162_rn(v00, v01);
            *(__nv_bfloat162*)(C + (size_t)(row0 + 8) * Nout + col) =
                __floats2bfloat162_rn(v10, v11);
        }
    }
}

// ---------------------------------------------------------------------------
// Final (byte-exact round 8): out = sigmoid(h3 @ Wd + bd + wide).
// ---------------------------------------------------------------------------
__global__ __launch_bounds__(256) void final_kernel(
    const float* __restrict__ Wd, const float* __restrict__ bd,
    float* __restrict__ out)
{
    const int warp = threadIdx.x >> 5;
    const int lane = threadIdx.x & 31;
    const int b    = blockIdx.x * 8 + warp;

    const __nv_bfloat16* h = g_h3b + (size_t)b * N3;
    const uint4 hv = ((const uint4*)h)[lane];
    const float4 w0 = ((const float4*)Wd)[lane * 2];
    const float4 w1 = ((const float4*)Wd)[lane * 2 + 1];

    const __nv_bfloat162* hp = (const __nv_bfloat162*)&hv;
    float s = 0.f;
    float2 p;
    p = __bfloat1622float2(hp[0]); s += p.x * w0.x + p.y * w0.y;
    p = __bfloat1622float2(hp[1]); s += p.x * w0.z + p.y * w0.w;
    p = __bfloat1622float2(hp[2]); s += p.x * w1.x + p.y * w1.y;
    p = __bfloat1622float2(hp[3]); s += p.x * w1.z + p.y * w1.w;

    #pragma unroll
    for (int o = 16; o; o >>= 1) s += __shfl_xor_sync(0xFFFFFFFFu, s, o);

    if (lane == 0) {
        const float logit = s + bd[0] + g_wide[b];
        out[b] = 1.0f / (1.0f + expf(-logit));
    }
}

// ---------------------------------------------------------------------------
extern "C" void kernel_launch(void* const* d_in, const int* in_sizes, int n_in,
                              void* d_out, int out_size)
{
    (void)in_sizes; (void)n_in; (void)out_size;

    const int*   tok = (const int*)d_in[0];
    const int*   m1  = (const int*)d_in[1];
    const int*   m2  = (const int*)d_in[2];
    const int*   m3  = (const int*)d_in[3];
    const int*   o1  = (const int*)d_in[4];
    const int*   o2  = (const int*)d_in[5];
    const int*   o3  = (const int*)d_in[6];
    const int*   o4  = (const int*)d_in[7];
    const float* we  = (const float*)d_in[8];
    const float* em1 = (const float*)d_in[9];
    const float* em2 = (const float*)d_in[10];
    const float* em3 = (const float*)d_in[11];
    const float* eo1 = (const float*)d_in[12];
    const float* eo2 = (const float*)d_in[13];
    const float* eo3 = (const float*)d_in[14];
    const float* eo4 = (const float*)d_in[15];
    const float* wm1 = (const float*)d_in[16];
    const float* wm2 = (const float*)d_in[17];
    const float* wm3 = (const float*)d_in[18];
    const float* wo1 = (const float*)d_in[19];
    const float* wo2 = (const float*)d_in[20];
    const float* wo3 = (const float*)d_in[21];
    const float* wo4 = (const float*)d_in[22];
    const float* W1  = (const float*)d_in[23];
    const float* b1  = (const float*)d_in[24];
    const float* W2  = (const float*)d_in[25];
    const float* b2  = (const float*)d_in[26];
    const float* W3  = (const float*)d_in[27];
    const float* b3  = (const float*)d_in[28];
    const float* Wd  = (const float*)d_in[29];
    const float* bd  = (const float*)d_in[30];
    float* out = (float*)d_out;

    void *p_embB, *p_h1, *p_h2, *p_h3, *p_wt1, *p_wt2, *p_wt3;
    cudaGetSymbolAddress(&p_embB, g_embB);
    cudaGetSymbolAddress(&p_h1,   g_h1b);
    cudaGetSymbolAddress(&p_h2,   g_h2b);
    cudaGetSymbolAddress(&p_h3,   g_h3b);
    cudaGetSymbolAddress(&p_wt1,  g_Wt1);
    cudaGetSymbolAddress(&p_wt2,  g_Wt2);
    cudaGetSymbolAddress(&p_wt3,  g_Wt3);

    const int SMEM_DYN = 3 * STAGE_BYTES;   // 96 KB
    static int smem_set = 0;
    if (!smem_set) {
        cudaFuncSetAttribute(gemm_tc_kernel,
                             cudaFuncAttributeMaxDynamicSharedMemorySize, SMEM_DYN);
        smem_set = 1;
    }

    // 0) fp32 -> bf16 table conversion (word_emb + mh tables)
    convert_kernel<<<(CV_TOT + 255) / 256, 256>>>(we, em1, em2, em3);

    // 1) embed (bf16 gathers) + weight prep
    embed_prep_kernel<<<B_SZ + 768 + 512 + 128, 256>>>(
        tok, m1, m2, m3, o1, o2, o3, o4,
        eo1, eo2, eo3, eo4,
        wm1, wm2, wm3, wo1, wo2, wo3, wo4,
        W1, W2, W3);

    // 2) GEMMs (round-8 champion)
    gemm_tc_kernel<<<dim3(N1 / 128, B_SZ / 128), 256, SMEM_DYN>>>(
        (const __nv_bfloat16*)p_embB, (const __nv_bfloat16*)p_wt1, b1,
        (__nv_bfloat16*)p_h1, N1, K1P);
    gemm_tc_kernel<<<dim3(N2 / 128, B_SZ / 128), 256, SMEM_DYN>>>(
        (const __nv_bfloat16*)p_h1, (const __nv_bfloat16*)p_wt2, b2,
        (__nv_bfloat16*)p_h2, N2, N1);
    gemm_tc_kernel<<<dim3(N3 / 128, B_SZ / 128), 256, SMEM_DYN>>>(
        (const __nv_bfloat16*)p_h2, (const __nv_bfloat16*)p_wt3, b3,
        (__nv_bfloat16*)p_h3, N3, N2);

    // 3) final GEMV + sigmoid
    final_kernel<<<B_SZ / 8, 256>>>(Wd, bd, out);
}

// round 16
// speedup vs baseline: 1.1596x; 1.0582x over previous
#include <cuda_runtime.h>
#include <cuda_bf16.h>
#include <math.h>
#include <stdint.h>

// ---------------------------------------------------------------------------
// WideDeep round 16: byte-exact resubmission of the round-8 champion
// (141.3 us), the best measured configuration across 8 subsequent variants.
// embed+prep fused kernel; tensor-core GEMMs (mma.m16n8k16 bf16, 128x128x64
// tiles, 3-stage cp.async, ldmatrix.x4, XOR swizzle, 2 CTAs/SM); vector final.
// ---------------------------------------------------------------------------

#define B_SZ   8192
#define L_TOK  32
#define L_MH   20
#define EMB    64
#define TOK_D  300
#define K1     748
#define K1P    768
#define N1     1024
#define N2     512
#define N3     256

__device__ __align__(16) __nv_bfloat16 g_embB[B_SZ * K1P];
__device__ __align__(16) __nv_bfloat16 g_h1b [B_SZ * N1];
__device__ __align__(16) __nv_bfloat16 g_h2b [B_SZ * N2];
__device__ __align__(16) __nv_bfloat16 g_h3b [B_SZ * N3];
__device__ __align__(16) __nv_bfloat16 g_Wt1 [N1 * K1P];
__device__ __align__(16) __nv_bfloat16 g_Wt2 [N2 * N1];
__device__ __align__(16) __nv_bfloat16 g_Wt3 [N3 * N2];
__device__ float g_wide[B_SZ];

__device__ __forceinline__ uint32_t smem_u32(const void* p) {
    uint32_t a;
    asm("{ .reg .u64 t; cvta.to.shared.u64 t, %1; cvt.u32.u64 %0, t; }"
        : "=r"(a) : "l"(p));
    return a;
}
__device__ __forceinline__ uint32_t bf2_bits(float x, float y) {
    __nv_bfloat162 v = __floats2bfloat162_rn(x, y);
    return *(uint32_t*)&v;
}

// ---------------------------------------------------------------------------
// Fused kernel 1: blocks [0, 8192) embed; blocks [8192, 9600) weight prep.
// ---------------------------------------------------------------------------
__global__ __launch_bounds__(256) void embed_prep_kernel(
    const int* __restrict__ tok, const int* __restrict__ m1,
    const int* __restrict__ m2,  const int* __restrict__ m3,
    const int* __restrict__ o1,  const int* __restrict__ o2,
    const int* __restrict__ o3,  const int* __restrict__ o4,
    const float* __restrict__ we,
    const float* __restrict__ em1, const float* __restrict__ em2,
    const float* __restrict__ em3,
    const float* __restrict__ eo1, const float* __restrict__ eo2,
    const float* __restrict__ eo3, const float* __restrict__ eo4,
    const float* __restrict__ wm1, const float* __restrict__ wm2,
    const float* __restrict__ wm3,
    const float* __restrict__ wo1, const float* __restrict__ wo2,
    const float* __restrict__ wo3, const float* __restrict__ wo4,
    const float* __restrict__ W1, const float* __restrict__ W2,
    const float* __restrict__ W3)
{
    const int tid = threadIdx.x;

    if (blockIdx.x >= B_SZ) {
        __shared__ float tile[32][33];
        const int bid = blockIdx.x - B_SZ;

        const float* W; __nv_bfloat16* Wt; int K, N, Kpad, t;
        if (bid < 768)       { W = W1; Wt = g_Wt1; K = K1; N = N1; Kpad = K1P; t = bid; }
        else if (bid < 1280) { W = W2; Wt = g_Wt2; K = N1; N = N2; Kpad = N1;  t = bid - 768; }
        else                 { W = W3; Wt = g_Wt3; K = N2; N = N3; Kpad = N2;  t = bid - 1280; }

        const int ktiles = Kpad >> 5;
        const int tk = t % ktiles, tn = t / ktiles;
        const int tx = tid & 31, ty = tid >> 5;

        #pragma unroll
        for (int i = 0; i < 4; i++) {
            const int k = tk * 32 + ty + i * 8;
            tile[tx][ty + i * 8] = (k < K) ? W[(size_t)k * N + tn * 32 + tx] : 0.f;
        }
        __syncthreads();

        const int p = tid & 15;
        #pragma unroll
        for (int h = 0; h < 2; h++) {
            const int n = (tid >> 4) + 16 * h;
            const uint32_t v = bf2_bits(tile[n][2 * p], tile[n][2 * p + 1]);
            *(uint32_t*)(Wt + (size_t)(tn * 32 + n) * Kpad + tk * 32 + p * 2) = v;
        }
        return;
    }

    const int b = blockIdx.x;

    __shared__ int s_tok[L_TOK];
    __shared__ int s_m1[L_MH], s_m2[L_MH], s_m3[L_MH];
    __shared__ int s_oh[4];
    __shared__ float4 s_part[2][75];

    if (tid < 32)       s_tok[tid]      = tok[b * L_TOK + tid];
    else if (tid < 52)  s_m1[tid - 32]  = m1[b * L_MH + tid - 32];
    else if (tid < 72)  s_m2[tid - 52]  = m2[b * L_MH + tid - 52];
    else if (tid < 92)  s_m3[tid - 72]  = m3[b * L_MH + tid - 72];
    else if (tid == 92) s_oh[0] = o1[b];
    else if (tid == 93) s_oh[1] = o2[b];
    else if (tid == 94) s_oh[2] = o3[b];
    else if (tid == 95) s_oh[3] = o4[b];
    __syncthreads();

    __nv_bfloat16* eb = g_embB + (size_t)b * K1P;

    float4 acc = make_float4(0.f, 0.f, 0.f, 0.f);
    if (tid < 225) {
        const int c = tid % 75, g = tid / 75;
        const int j0 = g * 11, j1 = (g < 2) ? j0 + 11 : 32;
        for (int j = j0; j < j1; j++) {
            const float4 v = *(const float4*)(we + (size_t)s_tok[j] * TOK_D + c * 4);
            acc.x += v.x; acc.y += v.y; acc.z += v.z; acc.w += v.w;
        }
        if (g > 0) s_part[g - 1][c] = acc;
    }

    if (tid >= 228 && tid < 233)
        ((uint2*)(eb + K1))[tid - 228] = make_uint2(0u, 0u);

    __syncthreads();

    if (tid < 75) {
        float4 t = acc;
        const float4 p0 = s_part[0][tid], p1 = s_part[1][tid];
        t.x = (t.x + p0.x + p1.x) * (1.0f / 32.0f);
        t.y = (t.y + p0.y + p1.y) * (1.0f / 32.0f);
        t.z = (t.z + p0.z + p1.z) * (1.0f / 32.0f);
        t.w = (t.w + p0.w + p1.w) * (1.0f / 32.0f);
        ((uint2*)eb)[tid] = make_uint2(bf2_bits(t.x, t.y), bf2_bits(t.z, t.w));
    } else if (tid >= 80 && tid < 128) {
        const int f = (tid - 80) >> 4, c = (tid - 80) & 15;
        const float* tab = (f == 0) ? em1 : (f == 1) ? em2 : em3;
        const int* sidx = (f == 0) ? s_m1 : (f == 1) ? s_m2 : s_m3;
        float4 s = make_float4(0.f, 0.f, 0.f, 0.f);
        #pragma unroll
        for (int j = 0; j < L_MH; j++) {
            const float4 v = *(const float4*)(tab + (size_t)sidx[j] * EMB + c * 4);
            s.x += v.x; s.y += v.y; s.z += v.z; s.w += v.w;
        }
        __nv_bfloat16* dst = eb + 300 + f * 64 + c * 4;
        *(uint2*)dst = make_uint2(bf2_bits(s.x * 0.05f, s.y * 0.05f),
                                  bf2_bits(s.z * 0.05f, s.w * 0.05f));
    } else if (tid >= 128 && tid < 192) {
        const int f = (tid - 128) >> 4, c = (tid - 128) & 15;
        const float* tab = (f == 0) ? eo1 : (f == 1) ? eo2 : (f == 2) ? eo3 : eo4;
        const float4 v = *(const float4*)(tab + (size_t)s_oh[f] * EMB + c * 4);
        __nv_bfloat16* dst = eb + 492 + f * 64 + c * 4;
        *(uint2*)dst = make_uint2(bf2_bits(v.x, v.y), bf2_bits(v.z, v.w));
    } else if (tid >= 192 && tid < 224) {
        const int lane = tid - 192;
        float s = 0.f;
        if (lane < L_MH)
            s = wm1[s_m1[lane]] + wm2[s_m2[lane]] + wm3[s_m3[lane]];
        #pragma unroll
        for (int o = 16; o; o >>= 1) s += __shfl_xor_sync(0xFFFFFFFFu, s, o);
        if (lane == 0) {
            s += wo1[s_oh[0]] + wo2[s_oh[1]] + wo3[s_oh[2]] + wo4[s_oh[3]];
            g_wide[b] = s;
        }
    }
}

// ---------------------------------------------------------------------------
// Tensor-core GEMM: C = relu(A[M,K] @ Bt[N,K]^T + bias) -> bf16
// 128x128x64 CTA tile, 256 thr (2x4 warps, 64x32 warp tile), mma m16n8k16,
// 3-stage cp.async pipeline (96 KB dynamic smem), ldmatrix.x4, 8-chunk XOR
// swizzle (128 B rows).
// ---------------------------------------------------------------------------
__device__ __forceinline__ void mma16816(float c[4], const uint32_t a[4],
                                         const uint32_t b[2])
{
    asm volatile(
        "mma.sync.aligned.m16n8k16.row.col.f32.bf16.bf16.f32 "
        "{%0,%1,%2,%3}, {%4,%5,%6,%7}, {%8,%9}, {%0,%1,%2,%3};"
        : "+f"(c[0]), "+f"(c[1]), "+f"(c[2]), "+f"(c[3])
        : "r"(a[0]), "r"(a[1]), "r"(a[2]), "r"(a[3]), "r"(b[0]), "r"(b[1]));
}

#define STAGE_BYTES 32768           // A 16K + B 16K (128 rows x 128 B each)

__global__ __launch_bounds__(256, 2) void gemm_tc_kernel(
    const __nv_bfloat16* __restrict__ A, const __nv_bfloat16* __restrict__ Bt,
    const float* __restrict__ bias, __nv_bfloat16* __restrict__ C,
    int Nout, int K)
{
    extern __shared__ __align__(1024) char sm[];   // 3 * STAGE_BYTES

    const int tid  = threadIdx.x;
    const int lane = tid & 31, warp = tid >> 5;
    const int wm   = warp & 1;
    const int wn   = warp >> 1;
    const int gid  = lane >> 2;
    const int tig  = lane & 3;
    const int bm   = blockIdx.y * 128, bn = blockIdx.x * 128;

    int offS[4], gA[4], gB[4];
    #pragma unroll
    for (int j = 0; j < 4; j++) {
        const int c = tid + j * 256;
        const int r = c >> 3, ch = c & 7;
        offS[j] = r * 128 + ((ch ^ (r & 7)) << 4);
        gA[j]   = (bm + r) * K + ch * 8;
        gB[j]   = (bn + r) * K + ch * 8;
    }

    const int NIT = K >> 6;   // K / 64

    const int q = lane >> 3, r8 = lane & 7;
    const int qa = q >> 1, qb = q & 1;
    uint32_t arow128[4]; int akey[4];
    #pragma unroll
    for (int mf = 0; mf < 4; mf++) {
        const int row = wm * 64 + mf * 16 + (q & 1) * 8 + r8;
        arow128[mf] = row * 128;
        akey[mf]    = row & 7;
    }
    uint32_t brow128[2]; int bkey[2];
    #pragma unroll
    for (int g = 0; g < 2; g++) {
        const int row = wn * 32 + g * 16 + (q >> 1) * 8 + r8;
        brow128[g] = row * 128;
        bkey[g]    = row & 7;
    }

    float acc[4][4][4];
    #pragma unroll
    for (int mf = 0; mf < 4; mf++)
        #pragma unroll
        for (int nf = 0; nf < 4; nf++)
            #pragma unroll
            for (int i = 0; i < 4; i++) acc[mf][nf][i] = 0.f;

    #define PREFETCH(stage, kofs)                                              \
        do {                                                                   \
            char* _s = sm + (stage) * STAGE_BYTES;                             \
            _Pragma("unroll")                                                  \
            for (int _j = 0; _j < 4; _j++) {                                   \
                uint32_t _da = smem_u32(_s + offS[_j]);                        \
                uint32_t _db = _da + 16384;                                    \
                asm volatile("cp.async.cg.shared.global [%0], [%1], 16;"       \
                             :: "r"(_da), "l"(A + gA[_j] + (kofs)) : "memory");\
                asm volatile("cp.async.cg.shared.global [%0], [%1], 16;"       \
                             :: "r"(_db), "l"(Bt + gB[_j] + (kofs)) : "memory");\
            }                                                                  \
        } while (0)

    PREFETCH(0, 0);
    asm volatile("cp.async.commit_group;" ::: "memory");
    PREFETCH(1, 64);
    asm volatile("cp.async.commit_group;" ::: "memory");

    for (int it = 0; it < NIT; it++) {
        asm volatile("cp.async.wait_group 1;" ::: "memory");
        __syncthreads();

        if (it + 2 < NIT) {
            const int st = it + 2;
            PREFETCH(st % 3, st * 64);
        }
        asm volatile("cp.async.commit_group;" ::: "memory");

        const uint32_t AsU = smem_u32(sm + (it % 3) * STAGE_BYTES);
        const uint32_t BsU = AsU + 16384;

        #pragma unroll
        for (int s = 0; s < 4; s++) {
            uint32_t af[4][4], bf[4][2];
            #pragma unroll
            for (int mf = 0; mf < 4; mf++) {
                const uint32_t addr =
                    AsU + arow128[mf] + ((((s << 1) + qa) ^ akey[mf]) << 4);
                asm volatile(
                    "ldmatrix.sync.aligned.m8n8.x4.shared.b16 {%0,%1,%2,%3}, [%4];"
                    : "=r"(af[mf][0]), "=r"(af[mf][1]),
                      "=r"(af[mf][2]), "=r"(af[mf][3])
                    : "r"(addr));
            }
            #pragma unroll
            for (int g = 0; g < 2; g++) {
                const uint32_t addr =
                    BsU + brow128[g] + ((((s << 1) + qb) ^ bkey[g]) << 4);
                asm volatile(
                    "ldmatrix.sync.aligned.m8n8.x4.shared.b16 {%0,%1,%2,%3}, [%4];"
                    : "=r"(bf[2 * g][0]), "=r"(bf[2 * g][1]),
                      "=r"(bf[2 * g + 1][0]), "=r"(bf[2 * g + 1][1])
                    : "r"(addr));
            }
            #pragma unroll
            for (int mf = 0; mf < 4; mf++)
                #pragma unroll
                for (int nf = 0; nf < 4; nf++)
                    mma16816(acc[mf][nf], af[mf], bf[nf]);
        }
    }
    #undef PREFETCH

    // epilogue: bias + ReLU -> bf16
    #pragma unroll
    for (int nf = 0; nf < 4; nf++) {
        const int col = bn + wn * 32 + nf * 8 + tig * 2;
        const float bv0 = bias[col], bv1 = bias[col + 1];
        #pragma unroll
        for (int mf = 0; mf < 4; mf++) {
            const int row0 = bm + wm * 64 + mf * 16 + gid;
            const float v00 = fmaxf(acc[mf][nf][0] + bv0, 0.f);
            const float v01 = fmaxf(acc[mf][nf][1] + bv1, 0.f);
            const float v10 = fmaxf(acc[mf][nf][2] + bv0, 0.f);
            const float v11 = fmaxf(acc[mf][nf][3] + bv1, 0.f);
            *(__nv_bfloat162*)(C + (size_t)row0 * Nout + col) =
                __floats2bfloat162_rn(v00, v01);
            *(__nv_bfloat162*)(C + (size_t)(row0 + 8) * Nout + col) =
                __floats2bfloat162_rn(v10, v11);
        }
    }
}

// ---------------------------------------------------------------------------
// Final: out = sigmoid(h3 @ Wd + bd + wide). One warp per row, vectorized.
// ---------------------------------------------------------------------------
__global__ __launch_bounds__(256) void final_kernel(
    const float* __restrict__ Wd, const float* __restrict__ bd,
    float* __restrict__ out)
{
    const int warp = threadIdx.x >> 5;
    const int lane = threadIdx.x & 31;
    const int b    = blockIdx.x * 8 + warp;

    const __nv_bfloat16* h = g_h3b + (size_t)b * N3;
    const uint4 hv = ((const uint4*)h)[lane];
    const float4 w0 = ((const float4*)Wd)[lane * 2];
    const float4 w1 = ((const float4*)Wd)[lane * 2 + 1];

    const __nv_bfloat162* hp = (const __nv_bfloat162*)&hv;
    float s = 0.f;
    float2 p;
    p = __bfloat1622float2(hp[0]); s += p.x * w0.x + p.y * w0.y;
    p = __bfloat1622float2(hp[1]); s += p.x * w0.z + p.y * w0.w;
    p = __bfloat1622float2(hp[2]); s += p.x * w1.x + p.y * w1.y;
    p = __bfloat1622float2(hp[3]); s += p.x * w1.z + p.y * w1.w;

    #pragma unroll
    for (int o = 16; o; o >>= 1) s += __shfl_xor_sync(0xFFFFFFFFu, s, o);

    if (lane == 0) {
        const float logit = s + bd[0] + g_wide[b];
        out[b] = 1.0f / (1.0f + expf(-logit));
    }
}

// ---------------------------------------------------------------------------
extern "C" void kernel_launch(void* const* d_in, const int* in_sizes, int n_in,
                              void* d_out, int out_size)
{
    (void)in_sizes; (void)n_in; (void)out_size;

    const int*   tok = (const int*)d_in[0];
    const int*   m1  = (const int*)d_in[1];
    const int*   m2  = (const int*)d_in[2];
    const int*   m3  = (const int*)d_in[3];
    const int*   o1  = (const int*)d_in[4];
    const int*   o2  = (const int*)d_in[5];
    const int*   o3  = (const int*)d_in[6];
    const int*   o4  = (const int*)d_in[7];
    const float* we  = (const float*)d_in[8];
    const float* em1 = (const float*)d_in[9];
    const float* em2 = (const float*)d_in[10];
    const float* em3 = (const float*)d_in[11];
    const float* eo1 = (const float*)d_in[12];
    const float* eo2 = (const float*)d_in[13];
    const float* eo3 = (const float*)d_in[14];
    const float* eo4 = (const float*)d_in[15];
    const float* wm1 = (const float*)d_in[16];
    const float* wm2 = (const float*)d_in[17];
    const float* wm3 = (const float*)d_in[18];
    const float* wo1 = (const float*)d_in[19];
    const float* wo2 = (const float*)d_in[20];
    const float* wo3 = (const float*)d_in[21];
    const float* wo4 = (const float*)d_in[22];
    const float* W1  = (const float*)d_in[23];
    const float* b1  = (const float*)d_in[24];
    const float* W2  = (const float*)d_in[25];
    const float* b2  = (const float*)d_in[26];
    const float* W3  = (const float*)d_in[27];
    const float* b3  = (const float*)d_in[28];
    const float* Wd  = (const float*)d_in[29];
    const float* bd  = (const float*)d_in[30];
    float* out = (float*)d_out;

    void *p_embB, *p_h1, *p_h2, *p_h3, *p_wt1, *p_wt2, *p_wt3;
    cudaGetSymbolAddress(&p_embB, g_embB);
    cudaGetSymbolAddress(&p_h1,   g_h1b);
    cudaGetSymbolAddress(&p_h2,   g_h2b);
    cudaGetSymbolAddress(&p_h3,   g_h3b);
    cudaGetSymbolAddress(&p_wt1,  g_Wt1);
    cudaGetSymbolAddress(&p_wt2,  g_Wt2);
    cudaGetSymbolAddress(&p_wt3,  g_Wt3);

    const int SMEM_DYN = 3 * STAGE_BYTES;   // 96 KB
    cudaFuncSetAttribute(gemm_tc_kernel,
                         cudaFuncAttributeMaxDynamicSharedMemorySize, SMEM_DYN);

    embed_prep_kernel<<<B_SZ + 768 + 512 + 128, 256>>>(
        tok, m1, m2, m3, o1, o2, o3, o4,
        we, em1, em2, em3, eo1, eo2, eo3, eo4,
        wm1, wm2, wm3, wo1, wo2, wo3, wo4,
        W1, W2, W3);

    gemm_tc_kernel<<<dim3(N1 / 128, B_SZ / 128), 256, SMEM_DYN>>>(
        (const __nv_bfloat16*)p_embB, (const __nv_bfloat16*)p_wt1, b1,
        (__nv_bfloat16*)p_h1, N1, K1P);
    gemm_tc_kernel<<<dim3(N2 / 128, B_SZ / 128), 256, SMEM_DYN>>>(
        (const __nv_bfloat16*)p_h1, (const __nv_bfloat16*)p_wt2, b2,
        (__nv_bfloat16*)p_h2, N2, N1);
    gemm_tc_kernel<<<dim3(N3 / 128, B_SZ / 128), 256, SMEM_DYN>>>(
        (const __nv_bfloat16*)p_h2, (const __nv_bfloat16*)p_wt3, b3,
        (__nv_bfloat16*)p_h3, N3, N2);

    final_kernel<<<B_SZ / 8, 256>>>(Wd, bd, out);
}